// round 1
// baseline (speedup 1.0000x reference)
#include <cuda_runtime.h>

// out[row, t] = x[row, t - s]  if 0 <= t - s < T else 0
// rows = B*M = 256, T = 160000, s = shifts[row] - max_shift in [-16000, 16000]

__global__ void random_shift_kernel(const float* __restrict__ x,
                                    const int* __restrict__ shifts,
                                    float* __restrict__ out,
                                    int T, int max_shift) {
    const int row = blockIdx.y;
    const int s = shifts[row] - max_shift;

    const int t0 = (blockIdx.x * blockDim.x + threadIdx.x) * 4;
    if (t0 >= T) return;   // T % 4 == 0, so t0..t0+3 all valid output indices

    const size_t base = (size_t)row * (size_t)T;
    const float* __restrict__ xr = x + base;

    const int src = t0 - s;
    float4 v;
    if (src >= 0 && src + 3 < T) {
        // fast path: all four source elements in range (misaligned but coalesced)
        v.x = __ldg(xr + src);
        v.y = __ldg(xr + src + 1);
        v.z = __ldg(xr + src + 2);
        v.w = __ldg(xr + src + 3);
    } else {
        float tmp[4];
#pragma unroll
        for (int i = 0; i < 4; ++i) {
            const int sc = src + i;
            tmp[i] = (sc >= 0 && sc < T) ? __ldg(xr + sc) : 0.0f;
        }
        v = make_float4(tmp[0], tmp[1], tmp[2], tmp[3]);
    }

    *reinterpret_cast<float4*>(out + base + t0) = v;
}

extern "C" void kernel_launch(void* const* d_in, const int* in_sizes, int n_in,
                              void* d_out, int out_size) {
    const float* x      = (const float*)d_in[0];
    const int*   shifts = (const int*)d_in[1];
    float*       out    = (float*)d_out;

    const int rows = in_sizes[1];              // B*M = 256
    const int T    = in_sizes[0] / rows;       // 160000
    const int max_shift = T / 10;              // 16000

    const int threads = 256;
    const int vec_per_row = (T + 3) / 4;       // 40000
    dim3 grid((vec_per_row + threads - 1) / threads, rows);
    random_shift_kernel<<<grid, threads>>>(x, shifts, out, T, max_shift);
}